// round 13
// baseline (speedup 1.0000x reference)
#include <cuda_runtime.h>
#include <math.h>

// EmbeddingToExpression: per-region MLP 16 -> 5 (exact-erf GELU) -> 1
//   R=1024, C=8192, DIN=16, E=5, NREG=2048. out[c,r] f32.
//
// R13 = R12 (weights in SMEM broadcast, cp.async ring, 3-term erf) with
// the register footprint cut to reach 8 CTAs/SM (occ 50%):
//  - chunk-wise x consumption: one float4 of x live at a time, consumed
//    by its 5 aligned weight float4s (20 FMAs) before the next chunk.
//    Peak regs ~50 -> __launch_bounds__(128, 8) (64-reg cap).
//  - DEPTH 2 ring (16 KB) so 8 CTAs fit in SMEM (~21.3 KB/CTA).
//  - wait_group 1: 32 warps x 2 KB = 64 KB/SM outstanding.

#define RR      1024
#define CC      8192
#define DIN     16
#define EE      5
#define CPB     256          // cells per block
#define RPB     4            // regions per block (one warp each)
#define PASSES  8            // CPB / 32
#define DEPTH   2            // pipeline ring depth
#define STAGE_B 2048         // 32 cells * 64 B per warp-pass
#define WPW     (DIN * EE)   // 80 weights per region

__device__ __forceinline__ unsigned sw128(unsigned o) {
    return o ^ ((o >> 3) & 0x70);
}
__device__ __forceinline__ void cp16(unsigned dst, const void* src) {
    asm volatile("cp.async.cg.shared.global [%0], [%1], 16;\n"
                 :: "r"(dst), "l"(src));
}
__device__ __forceinline__ void cp_commit() {
    asm volatile("cp.async.commit_group;\n" ::: "memory");
}
__device__ __forceinline__ void cp_wait1() {
    asm volatile("cp.async.wait_group 1;\n" ::: "memory");
}

// 1 + erf(x), branchless. Abramowitz-Stegun 7.1.25, |abs err| <= 2.5e-5.
__device__ __forceinline__ float erf1p(float x) {
    const float p  = 0.47047f;
    const float a1 = 0.3480242f, a2 = -0.0958798f, a3 = 0.7478556f;
    float ax = fabsf(x);
    float t  = __fdividef(1.0f, fmaf(p, ax, 1.0f));   // MUFU.RCP
    float r  = fmaf(a3, t, a2);
    r = fmaf(r, t, a1);
    r = r * t;
    float u = r * __expf(-x * x);                     // MUFU.EX2
    return 1.0f + copysignf(1.0f - u, x);
}

__global__ __launch_bounds__(128, 8)
void e2e_kernel(const float* __restrict__ emb,
                const void*  __restrict__ oi,     // int32 or int64, detected
                const float* __restrict__ W1,     // [NREG, DIN, E]
                const float* __restrict__ b1,     // [NREG, E]
                const float* __restrict__ Wf,     // [NREG, E, 1]
                float* __restrict__ out)          // [C, R]
{
    __shared__ __align__(1024) char s_stage[RPB * DEPTH * STAGE_B]; // 16 KB
    __shared__ float s_out[RPB * CPB];                              // 4 KB
    __shared__ __align__(16) float s_w[RPB * WPW];                  // 1.25 KB
    __shared__ int   s_is64;

    // Detect regions_oi width (values < 2048 => int64 high words are 0).
    if (threadIdx.x == 0) {
        const int* w = (const int*)oi;
        int all0 = 1;
        #pragma unroll
        for (int k = 0; k < 32; k++) all0 &= (w[2 * k + 1] == 0);
        s_is64 = all0;
    }
    __syncthreads();

    const int warp = threadIdx.x >> 5;
    const int lane = threadIdx.x & 31;
    const int r    = blockIdx.x * RPB + warp;   // region group = FAST grid dim
    const int c0   = blockIdx.y * CPB;

    int reg;
    if (s_is64) reg = (int)((const long long*)oi)[r];
    else        reg = ((const int*)oi)[r];

    // ---- hoisted swizzled offsets + pipeline bases ----
    const char* gsrc = (const char*)(emb + ((size_t)r * CC + c0) * DIN);
    char*       wbuf = s_stage + warp * (DEPTH * STAGE_B);
    const unsigned sbase = (unsigned)__cvta_generic_to_shared(wbuf);
    unsigned po[4], co[4];
    #pragma unroll
    for (int k = 0; k < 4; k++) {
        po[k] = sw128(k * 512 + lane * 16);     // producer dst offsets
        co[k] = sw128(lane * 64 + k * 16);      // consumer src offsets
    }
    const unsigned goff = lane * 16;

    // ---- start DRAM traffic first: prologue stage 0 ----
    {
        const char* s = gsrc + goff;
        cp16(sbase + po[0], s);
        cp16(sbase + po[1], s + 512);
        cp16(sbase + po[2], s + 1024);
        cp16(sbase + po[3], s + 1536);
        cp_commit();
    }

    // ---- stage this warp's 80 weights (prescaled by 1/sqrt2) to SMEM ----
    const float KI = 0.70710678118654752f;      // 1/sqrt(2)
    const float KQ = 0.70710678118654752f;      // 0.5/KI
    {
        const float* wrow = W1 + (size_t)reg * WPW;
        float* wsm = s_w + warp * WPW;
        #pragma unroll
        for (int j = 0; j < 3; j++) {
            int idx = lane * 3 + j;             // 0..95 covers 0..79
            if (idx < WPW) wsm[idx] = wrow[idx] * KI;
        }
        __syncwarp();
    }
    float bb[EE], wq[EE];
    #pragma unroll
    for (int e = 0; e < EE; e++) {
        bb[e] = b1[reg * EE + e] * KI;
        wq[e] = Wf[reg * EE + e] * KQ;          // 0.5/KI * wf
    }
    const float4* w4 = (const float4*)(s_w + warp * WPW);   // 20 vec4

    #pragma unroll
    for (int p = 0; p < PASSES; p++) {
        const int g = p + DEPTH - 1;
        if (g < PASSES) {
            const unsigned slot = sbase + (g % DEPTH) * STAGE_B;
            const char* s = gsrc + g * STAGE_B + goff;
            cp16(slot + po[0], s);
            cp16(slot + po[1], s + 512);
            cp16(slot + po[2], s + 1024);
            cp16(slot + po[3], s + 1536);
        }
        cp_commit();
        cp_wait1();   // all but newest group done => stage p landed

        // ---- compute pass p: chunk-wise x (one float4 live at a time),
        //      weights via LDS.128 broadcast (warp-uniform address) ----
        const char* xb = wbuf + (p % DEPTH) * STAGE_B;

        float h[EE] = { bb[0], bb[1], bb[2], bb[3], bb[4] };
        #pragma unroll
        for (int q = 0; q < 4; q++) {           // 4 x-chunks of 4 values
            float4 xv = *(const float4*)(xb + co[q]);
            float xc[4] = { xv.x, xv.y, xv.z, xv.w };
            #pragma unroll
            for (int j = 0; j < 5; j++) {       // 5 weight vec4s per chunk
                float4 wv = w4[q * 5 + j];
                const int f = q * 20 + j * 4;   // flat weight index
                h[(f + 0) % 5] = fmaf(xc[(f + 0) / 5 - 4 * q], wv.x, h[(f + 0) % 5]);
                h[(f + 1) % 5] = fmaf(xc[(f + 1) / 5 - 4 * q], wv.y, h[(f + 1) % 5]);
                h[(f + 2) % 5] = fmaf(xc[(f + 2) / 5 - 4 * q], wv.z, h[(f + 2) % 5]);
                h[(f + 3) % 5] = fmaf(xc[(f + 3) / 5 - 4 * q], wv.w, h[(f + 3) % 5]);
            }
        }

        // gelu(h)*wf == h' * (1 + erf(h')) * (0.5/KI)*wf,  h' = h/sqrt(2)
        float q0 = erf1p(h[0]);
        float q1 = erf1p(h[1]);
        float q2 = erf1p(h[2]);
        float q3 = erf1p(h[3]);
        float q4 = erf1p(h[4]);
        float acc = (h[0] * wq[0]) * q0;
        acc = fmaf(h[1] * wq[1], q1, acc);
        acc = fmaf(h[2] * wq[2], q2, acc);
        acc = fmaf(h[3] * wq[3], q3, acc);
        acc = fmaf(h[4] * wq[4], q4, acc);

        s_out[warp * CPB + (p * 32 + lane)] = acc;
    }
    __syncthreads();

    // ---- transposed write: 16B per thread-cell; adjacent blockIdx.x
    //      supplies the neighboring half-sector -> L2 write-merge.
    #pragma unroll
    for (int cc = 0; cc < CPB; cc += 128) {
        const int c = cc + threadIdx.x;
        float4 o;
        o.x = s_out[0 * CPB + c];
        o.y = s_out[1 * CPB + c];
        o.z = s_out[2 * CPB + c];
        o.w = s_out[3 * CPB + c];
        float* op = out + (size_t)(c0 + c) * RR + (size_t)blockIdx.x * RPB;
        *(float4*)op = o;
    }
}

extern "C" void kernel_launch(void* const* d_in, const int* in_sizes, int n_in,
                              void* d_out, int out_size)
{
    const float* emb = (const float*)d_in[0];   // [R, C, DIN] f32
    const void*  oi  = d_in[1];                 // [R] int32/int64
    const float* W1  = (const float*)d_in[2];   // [NREG, DIN, E]
    const float* b1  = (const float*)d_in[3];   // [NREG, E]
    const float* Wf  = (const float*)d_in[4];   // [NREG, E, 1]
    float* out = (float*)d_out;                 // [C, R]

    dim3 grid(RR / RPB, CC / CPB);              // (256, 32) region-group fast
    e2e_kernel<<<grid, 128>>>(emb, oi, W1, b1, Wf, out);
}

// round 14
// speedup vs baseline: 1.0068x; 1.0068x over previous
#include <cuda_runtime.h>
#include <math.h>

// EmbeddingToExpression: per-region MLP 16 -> 5 (exact-erf GELU) -> 1
//   R=1024, C=8192, DIN=16, E=5, NREG=2048. out[c,r] f32.
//
// R14: full-sector output writes. Occupancy sweep (24/35/47%) proved
// HBM rate is pinned at ~6.1 TB/s; effective traffic audit shows +32MiB
// over payload == half-sector (16B) write RMW from RPB=4. This kernel:
// 256-thr blocks, 8 warps = 8 regions -> each thread stores 8 region
// values = one full 32B sector (2 adjacent float4s), zero RMW.
// Keeps R12/R13 machinery: weights in SMEM broadcast (LDS.128,
// warp-uniform), chunk-wise x (64 regs), DEPTH-2 cp.async ring,
// 3-term A&S erf. SMEM ~42.8 KB -> 4 CTAs/SM = 32 warps (occ 50%).

#define RR      1024
#define CC      8192
#define DIN     16
#define EE      5
#define CPB     256          // cells per block
#define RPB     8            // regions per block (one warp each)
#define PASSES  8            // CPB / 32
#define DEPTH   2            // pipeline ring depth
#define STAGE_B 2048         // 32 cells * 64 B per warp-pass
#define WPW     (DIN * EE)   // 80 weights per region

__device__ __forceinline__ unsigned sw128(unsigned o) {
    return o ^ ((o >> 3) & 0x70);
}
__device__ __forceinline__ void cp16(unsigned dst, const void* src) {
    asm volatile("cp.async.cg.shared.global [%0], [%1], 16;\n"
                 :: "r"(dst), "l"(src));
}
__device__ __forceinline__ void cp_commit() {
    asm volatile("cp.async.commit_group;\n" ::: "memory");
}
__device__ __forceinline__ void cp_wait1() {
    asm volatile("cp.async.wait_group 1;\n" ::: "memory");
}

// 1 + erf(x), branchless. Abramowitz-Stegun 7.1.25, |abs err| <= 2.5e-5.
__device__ __forceinline__ float erf1p(float x) {
    const float p  = 0.47047f;
    const float a1 = 0.3480242f, a2 = -0.0958798f, a3 = 0.7478556f;
    float ax = fabsf(x);
    float t  = __fdividef(1.0f, fmaf(p, ax, 1.0f));   // MUFU.RCP
    float r  = fmaf(a3, t, a2);
    r = fmaf(r, t, a1);
    r = r * t;
    float u = r * __expf(-x * x);                     // MUFU.EX2
    return 1.0f + copysignf(1.0f - u, x);
}

__global__ __launch_bounds__(256, 4)
void e2e_kernel(const float* __restrict__ emb,
                const void*  __restrict__ oi,     // int32 or int64, detected
                const float* __restrict__ W1,     // [NREG, DIN, E]
                const float* __restrict__ b1,     // [NREG, E]
                const float* __restrict__ Wf,     // [NREG, E, 1]
                float* __restrict__ out)          // [C, R]
{
    __shared__ __align__(1024) char s_stage[RPB * DEPTH * STAGE_B]; // 32 KB
    __shared__ float s_out[RPB * CPB];                              // 8 KB
    __shared__ __align__(16) float s_w[RPB * WPW];                  // 2.5 KB
    __shared__ int   s_is64;

    // Detect regions_oi width (values < 2048 => int64 high words are 0).
    if (threadIdx.x == 0) {
        const int* w = (const int*)oi;
        int all0 = 1;
        #pragma unroll
        for (int k = 0; k < 32; k++) all0 &= (w[2 * k + 1] == 0);
        s_is64 = all0;
    }
    __syncthreads();

    const int warp = threadIdx.x >> 5;
    const int lane = threadIdx.x & 31;
    const int r    = blockIdx.x * RPB + warp;   // region group = FAST grid dim
    const int c0   = blockIdx.y * CPB;

    int reg;
    if (s_is64) reg = (int)((const long long*)oi)[r];
    else        reg = ((const int*)oi)[r];

    // ---- hoisted swizzled offsets + pipeline bases ----
    const char* gsrc = (const char*)(emb + ((size_t)r * CC + c0) * DIN);
    char*       wbuf = s_stage + warp * (DEPTH * STAGE_B);
    const unsigned sbase = (unsigned)__cvta_generic_to_shared(wbuf);
    unsigned po[4], co[4];
    #pragma unroll
    for (int k = 0; k < 4; k++) {
        po[k] = sw128(k * 512 + lane * 16);     // producer dst offsets
        co[k] = sw128(lane * 64 + k * 16);      // consumer src offsets
    }
    const unsigned goff = lane * 16;

    // ---- start DRAM traffic first: prologue stage 0 ----
    {
        const char* s = gsrc + goff;
        cp16(sbase + po[0], s);
        cp16(sbase + po[1], s + 512);
        cp16(sbase + po[2], s + 1024);
        cp16(sbase + po[3], s + 1536);
        cp_commit();
    }

    // ---- stage this warp's 80 weights (prescaled by 1/sqrt2) to SMEM ----
    const float KI = 0.70710678118654752f;      // 1/sqrt(2)
    const float KQ = 0.70710678118654752f;      // 0.5/KI
    {
        const float* wrow = W1 + (size_t)reg * WPW;
        float* wsm = s_w + warp * WPW;
        #pragma unroll
        for (int j = 0; j < 3; j++) {
            int idx = lane * 3 + j;             // 0..95 covers 0..79
            if (idx < WPW) wsm[idx] = wrow[idx] * KI;
        }
        __syncwarp();
    }
    float bb[EE], wq[EE];
    #pragma unroll
    for (int e = 0; e < EE; e++) {
        bb[e] = b1[reg * EE + e] * KI;
        wq[e] = Wf[reg * EE + e] * KQ;          // 0.5/KI * wf
    }
    const float4* w4 = (const float4*)(s_w + warp * WPW);   // 20 vec4

    #pragma unroll
    for (int p = 0; p < PASSES; p++) {
        const int g = p + DEPTH - 1;
        if (g < PASSES) {
            const unsigned slot = sbase + (g % DEPTH) * STAGE_B;
            const char* s = gsrc + g * STAGE_B + goff;
            cp16(slot + po[0], s);
            cp16(slot + po[1], s + 512);
            cp16(slot + po[2], s + 1024);
            cp16(slot + po[3], s + 1536);
        }
        cp_commit();
        cp_wait1();   // all but newest group done => stage p landed

        // ---- compute pass p: chunk-wise x (one float4 live at a time),
        //      weights via LDS.128 broadcast (warp-uniform address) ----
        const char* xb = wbuf + (p % DEPTH) * STAGE_B;

        float h[EE] = { bb[0], bb[1], bb[2], bb[3], bb[4] };
        #pragma unroll
        for (int q = 0; q < 4; q++) {           // 4 x-chunks of 4 values
            float4 xv = *(const float4*)(xb + co[q]);
            float xc[4] = { xv.x, xv.y, xv.z, xv.w };
            #pragma unroll
            for (int j = 0; j < 5; j++) {       // 5 weight vec4s per chunk
                float4 wv = w4[q * 5 + j];
                const int f = q * 20 + j * 4;   // flat weight index
                h[(f + 0) % 5] = fmaf(xc[(f + 0) / 5 - 4 * q], wv.x, h[(f + 0) % 5]);
                h[(f + 1) % 5] = fmaf(xc[(f + 1) / 5 - 4 * q], wv.y, h[(f + 1) % 5]);
                h[(f + 2) % 5] = fmaf(xc[(f + 2) / 5 - 4 * q], wv.z, h[(f + 2) % 5]);
                h[(f + 3) % 5] = fmaf(xc[(f + 3) / 5 - 4 * q], wv.w, h[(f + 3) % 5]);
            }
        }

        // gelu(h)*wf == h' * (1 + erf(h')) * (0.5/KI)*wf,  h' = h/sqrt(2)
        float q0 = erf1p(h[0]);
        float q1 = erf1p(h[1]);
        float q2 = erf1p(h[2]);
        float q3 = erf1p(h[3]);
        float q4 = erf1p(h[4]);
        float acc = (h[0] * wq[0]) * q0;
        acc = fmaf(h[1] * wq[1], q1, acc);
        acc = fmaf(h[2] * wq[2], q2, acc);
        acc = fmaf(h[3] * wq[3], q3, acc);
        acc = fmaf(h[4] * wq[4], q4, acc);

        s_out[warp * CPB + (p * 32 + lane)] = acc;
    }
    __syncthreads();

    // ---- transposed write: thread t owns cell c0+t, emits 8 region
    //      values = 32 B contiguous (one FULL sector; r base 8-aligned).
    //      No half-sector RMW, no reliance on cross-CTA L2 merging.
    const int c = threadIdx.x;
    float4 o0, o1;
    o0.x = s_out[0 * CPB + c];
    o0.y = s_out[1 * CPB + c];
    o0.z = s_out[2 * CPB + c];
    o0.w = s_out[3 * CPB + c];
    o1.x = s_out[4 * CPB + c];
    o1.y = s_out[5 * CPB + c];
    o1.z = s_out[6 * CPB + c];
    o1.w = s_out[7 * CPB + c];

    float* op = out + (size_t)(c0 + c) * RR + (size_t)blockIdx.x * RPB;
    ((float4*)op)[0] = o0;
    ((float4*)op)[1] = o1;
}

extern "C" void kernel_launch(void* const* d_in, const int* in_sizes, int n_in,
                              void* d_out, int out_size)
{
    const float* emb = (const float*)d_in[0];   // [R, C, DIN] f32
    const void*  oi  = d_in[1];                 // [R] int32/int64
    const float* W1  = (const float*)d_in[2];   // [NREG, DIN, E]
    const float* b1  = (const float*)d_in[3];   // [NREG, E]
    const float* Wf  = (const float*)d_in[4];   // [NREG, E, 1]
    float* out = (float*)d_out;                 // [C, R]

    dim3 grid(RR / RPB, CC / CPB);              // (128, 32) region-group fast
    e2e_kernel<<<grid, 256>>>(emb, oi, W1, b1, Wf, out);
}